// round 4
// baseline (speedup 1.0000x reference)
#include <cuda_runtime.h>

#define N_NODES 50000
#define N_EDGES 1600000
#define IN_C    128
#define HEADS   4
#define OUT_C   16
#define HC      64   // HEADS*OUT_C

// ---------------- scratch (static device globals; no allocs allowed) --------
__device__ __align__(16) float g_xw[N_NODES * HC];      // projected features
__device__ __align__(16) float g_asrc[N_NODES * HEADS]; // per-node src logits
__device__ __align__(16) float g_adst[N_NODES * HEADS]; // per-node dst logits
__device__ __align__(16) int   g_cnt[N_NODES];          // in-degree histogram
__device__ __align__(16) int   g_rowptr[N_NODES + 1];   // CSR row pointers
__device__ __align__(16) int   g_cursor[N_NODES];       // reorder cursors
__device__ __align__(16) int   g_ssrc[N_EDGES];         // src sorted by dst

// ---------------- K0: zero histogram ----------------------------------------
__global__ void k_zero(int n) {
    int t = blockIdx.x * blockDim.x + threadIdx.x;
    if (t < n) g_cnt[t] = 0;
}

// ---------------- K1: xw = x @ W   ([N,128]@[128,64]) -----------------------
// 256 threads, 64 rows/block. Thread = 4 rows x 4 cols, packed f32x2 FMA.
__global__ void k_proj(const float* __restrict__ x, const float* __restrict__ W,
                       int n) {
    extern __shared__ float smem[];
    float* sW = smem;              // IN_C*HC = 8192 floats
    float* sx = smem + IN_C * HC;  // 64*IN_C = 8192 floats
    int tid = threadIdx.x;
    int row0 = blockIdx.x * 64;

    for (int i = tid; i < IN_C * HC / 4; i += 256)
        ((float4*)sW)[i] = ((const float4*)W)[i];
    for (int i = tid; i < 64 * IN_C / 4; i += 256) {
        int r = i >> 5;
        float4 v = make_float4(0.f, 0.f, 0.f, 0.f);
        if (row0 + r < n) v = ((const float4*)x)[(size_t)(row0 + r) * 32 + (i & 31)];
        ((float4*)sx)[i] = v;
    }
    __syncthreads();

    int rg = tid >> 4;
    int c4 = (tid & 15) * 4;
    unsigned long long a0[4], a1[4];
#pragma unroll
    for (int i = 0; i < 4; i++) { a0[i] = 0ull; a1[i] = 0ull; }

#pragma unroll 4
    for (int k = 0; k < IN_C; k++) {
        float4 w = *(const float4*)&sW[k * HC + c4];
        unsigned long long w01, w23;
        asm("mov.b64 %0, {%1, %2};" : "=l"(w01) : "f"(w.x), "f"(w.y));
        asm("mov.b64 %0, {%1, %2};" : "=l"(w23) : "f"(w.z), "f"(w.w));
#pragma unroll
        for (int i = 0; i < 4; i++) {
            float xv = sx[(rg * 4 + i) * IN_C + k];
            unsigned long long xp;
            asm("mov.b64 %0, {%1, %1};" : "=l"(xp) : "f"(xv));
            asm("fma.rn.f32x2 %0, %1, %2, %0;" : "+l"(a0[i]) : "l"(xp), "l"(w01));
            asm("fma.rn.f32x2 %0, %1, %2, %0;" : "+l"(a1[i]) : "l"(xp), "l"(w23));
        }
    }
#pragma unroll
    for (int i = 0; i < 4; i++) {
        int row = row0 + rg * 4 + i;
        if (row < n) {
            float4 o;
            asm("mov.b64 {%0, %1}, %2;" : "=f"(o.x), "=f"(o.y) : "l"(a0[i]));
            asm("mov.b64 {%0, %1}, %2;" : "=f"(o.z), "=f"(o.w) : "l"(a1[i]));
            *(float4*)&g_xw[row * HC + c4] = o;
        }
    }
}

// ---------------- K2: per-node attention logits -----------------------------
__global__ void k_att(const float* __restrict__ att_src,
                      const float* __restrict__ att_dst, int n) {
    int t = blockIdx.x * blockDim.x + threadIdx.x;
    if (t >= n * HEADS) return;
    int node = t >> 2, h = t & 3;
    const float4* xp = (const float4*)(g_xw + node * HC + h * OUT_C);
    const float4* as = (const float4*)(att_src + h * OUT_C);
    const float4* ad = (const float4*)(att_dst + h * OUT_C);
    float ss = 0.f, sd = 0.f;
#pragma unroll
    for (int i = 0; i < 4; i++) {
        float4 v = xp[i], a = as[i], b = ad[i];
        ss += v.x * a.x + v.y * a.y + v.z * a.z + v.w * a.w;
        sd += v.x * b.x + v.y * b.y + v.z * b.z + v.w * b.w;
    }
    g_asrc[t] = ss;
    g_adst[t] = sd;
}

// ---------------- K3: in-degree histogram ------------------------------------
__global__ void k_hist(const int* __restrict__ ei, int e) {
    int t = blockIdx.x * blockDim.x + threadIdx.x;
    if (t < e) atomicAdd(&g_cnt[ei[e + t]], 1);
}

// ---------------- K4: exclusive scan (single block, 1024 threads) -----------
__global__ void k_scan(int n, int e) {
    __shared__ int wsum[32];
    int t = threadIdx.x, lane = t & 31, wid = t >> 5;
    int chunk = (n + 1023) >> 10;
    int beg = t * chunk;
    int end = min(n, beg + chunk);
    int sum = 0;
    for (int i = beg; i < end; i++) sum += g_cnt[i];
    int v = sum;
#pragma unroll
    for (int o = 1; o < 32; o <<= 1) {
        int u = __shfl_up_sync(0xffffffffu, v, o);
        if (lane >= o) v += u;
    }
    if (lane == 31) wsum[wid] = v;
    __syncthreads();
    if (wid == 0) {
        int w = wsum[lane];
#pragma unroll
        for (int o = 1; o < 32; o <<= 1) {
            int u = __shfl_up_sync(0xffffffffu, w, o);
            if (lane >= o) w += u;
        }
        wsum[lane] = w;
    }
    __syncthreads();
    int run = v - sum + (wid > 0 ? wsum[wid - 1] : 0);
    for (int i = beg; i < end; i++) {
        int c = g_cnt[i];
        g_rowptr[i] = run;
        g_cursor[i] = run;
        run += c;
    }
    if (t == 0) g_rowptr[n] = e;
}

// ---------------- K5: reorder src by dst -------------------------------------
__global__ void k_reorder(const int* __restrict__ ei, int e) {
    int t = blockIdx.x * blockDim.x + threadIdx.x;
    if (t >= e) return;
    int s = ei[t];
    int d = ei[e + t];
    int pos = atomicAdd(&g_cursor[d], 1);
    g_ssrc[pos] = s;
}

// ---------------- K6: fused gather-aggregate + softmax + ELU + out proj -----
// One warp per destination node. Lane l accumulates channels l and l+32.
// Edges processed in chunks of 32 (coalesced src load), groups of 4:
// lanes 0-15 compute exp for (4 edges x 4 heads) in parallel.
__global__ void k_agg(const float* __restrict__ bias,
                      const float* __restrict__ W_out,
                      const float* __restrict__ b_out,
                      float* __restrict__ y, int n) {
    int warp = (blockIdx.x * blockDim.x + threadIdx.x) >> 5;
    int lane = threadIdx.x & 31;
    if (warp >= n) return;
    int d = warp;
    int beg = g_rowptr[d];
    int end = g_rowptr[d + 1];

    float adst4 = g_adst[d * 4 + (lane & 3)];  // lane 4jj+h holds adst[h]
    float acc0 = 0.f, acc1 = 0.f;              // channels: lane, lane+32
    float exsum = 0.f;                         // lanes 0-15: per-(jj,h) partials
    int hA = lane >> 4;                        // head of channel lane (0/1)
    int hB = 2 + hA;                           // head of channel lane+32 (2/3)

    for (int i = beg; i < end; i += 32) {
        int m = end - i; if (m > 32) m = 32;
        int s_l = (lane < m) ? g_ssrc[i + lane] : 0;

        for (int j0 = 0; j0 < m; j0 += 4) {
            int s0 = __shfl_sync(0xffffffffu, s_l, j0);
            int s1 = __shfl_sync(0xffffffffu, s_l, j0 + 1);
            int s2 = __shfl_sync(0xffffffffu, s_l, j0 + 2);
            int s3 = __shfl_sync(0xffffffffu, s_l, j0 + 3);

            // lanes 0-15: edge jj = lane>>2, head h = lane&3
            int jj = lane >> 2;
            int sx = (jj == 0) ? s0 : (jj == 1) ? s1 : (jj == 2) ? s2 : s3;
            float ex = 0.f;
            if (lane < 16 && j0 + jj < m) {
                float a = g_asrc[sx * 4 + (lane & 3)] + adst4;
                a = a > 0.f ? a : 0.2f * a;
                ex = __expf(a);
            }
            exsum += ex;  // only lanes 0-15 meaningful

            // broadcast ex to all lanes per (edge, needed head)
            float e0A = __shfl_sync(0xffffffffu, ex, hA);
            float e0B = __shfl_sync(0xffffffffu, ex, hB);
            float e1A = __shfl_sync(0xffffffffu, ex, 4 + hA);
            float e1B = __shfl_sync(0xffffffffu, ex, 4 + hB);
            float e2A = __shfl_sync(0xffffffffu, ex, 8 + hA);
            float e2B = __shfl_sync(0xffffffffu, ex, 8 + hB);
            float e3A = __shfl_sync(0xffffffffu, ex, 12 + hA);
            float e3B = __shfl_sync(0xffffffffu, ex, 12 + hB);

            acc0 += e0A * g_xw[s0 * HC + lane];
            acc1 += e0B * g_xw[s0 * HC + 32 + lane];
            acc0 += e1A * g_xw[s1 * HC + lane];
            acc1 += e1B * g_xw[s1 * HC + 32 + lane];
            acc0 += e2A * g_xw[s2 * HC + lane];
            acc1 += e2B * g_xw[s2 * HC + 32 + lane];
            acc0 += e3A * g_xw[s3 * HC + lane];
            acc1 += e3B * g_xw[s3 * HC + 32 + lane];
        }
    }

    // per-head denominators: reduce exsum over jj (lanes h, h+4, h+8, h+12)
    exsum += __shfl_xor_sync(0xffffffffu, exsum, 4);
    exsum += __shfl_xor_sync(0xffffffffu, exsum, 8);
    float inv = 1.f / (exsum + 1e-16f);           // valid in lanes 0-3
    float invA = __shfl_sync(0xffffffffu, inv, hA);
    float invB = __shfl_sync(0xffffffffu, inv, hB);

    // normalize + bias + ELU + output projection
    float oA = acc0 * invA + bias[lane];
    float oB = acc1 * invB + bias[32 + lane];
    oA = oA > 0.f ? oA : __expf(oA) - 1.f;
    oB = oB > 0.f ? oB : __expf(oB) - 1.f;
    float p = oA * W_out[lane] + oB * W_out[32 + lane];
#pragma unroll
    for (int o = 16; o > 0; o >>= 1)
        p += __shfl_xor_sync(0xffffffffu, p, o);
    if (lane == 0) y[d] = p + b_out[0];
}

// ---------------- launch -----------------------------------------------------
extern "C" void kernel_launch(void* const* d_in, const int* in_sizes, int n_in,
                              void* d_out, int out_size) {
    const float* x       = (const float*)d_in[0];
    const int*   ei      = (const int*)d_in[1];
    const float* W       = (const float*)d_in[2];
    const float* att_src = (const float*)d_in[3];
    const float* att_dst = (const float*)d_in[4];
    const float* bias    = (const float*)d_in[5];
    const float* W_out   = (const float*)d_in[6];
    const float* b_out   = (const float*)d_in[7];
    float*       y       = (float*)d_out;

    int n = in_sizes[0] / IN_C;   // 50000
    int e = in_sizes[1] / 2;      // 1600000

    const int B = 256;
    const int proj_smem = (IN_C * HC + 64 * IN_C) * (int)sizeof(float); // 64KB
    cudaFuncSetAttribute(k_proj, cudaFuncAttributeMaxDynamicSharedMemorySize,
                         proj_smem);

    k_zero<<<(n + B - 1) / B, B>>>(n);
    k_proj<<<(n + 63) / 64, 256, proj_smem>>>(x, W, n);
    k_att<<<(n * HEADS + B - 1) / B, B>>>(att_src, att_dst, n);
    k_hist<<<(e + B - 1) / B, B>>>(ei, e);
    k_scan<<<1, 1024>>>(n, e);
    k_reorder<<<(e + B - 1) / B, B>>>(ei, e);
    k_agg<<<(n * 32 + B - 1) / B, B>>>(bias, W_out, b_out, y, n);
}